// round 2
// baseline (speedup 1.0000x reference)
#include <cuda_runtime.h>

#define QB       128     // queries per CTA
#define NTHREADS 256
#define CAP      2048    // worklist capacity (expected ~650/CTA)
#define KK       27      // kernel points
#define CH       64      // CIN == COUT
#define NB       (8*KK)  // (owner warp, k) buckets = 216

__global__ __launch_bounds__(NTHREADS, 4) void kpconv_kernel(
    const float* __restrict__ q_pts,   // [N,3]
    const float* __restrict__ s_pts,   // [M,3]
    const int*   __restrict__ inds,    // [N,32]
    const float* __restrict__ x,       // [M,64]
    const float* __restrict__ W,       // [27,64,64]
    const float* __restrict__ kpts,    // [27,3]
    float* __restrict__ out,           // [N,64]
    int N, int M)
{
    extern __shared__ float sm[];
    float*    out_acc = sm;                    // QB*CH
    float*    qp      = out_acc + QB * CH;     // QB*3
    float*    kp      = qp + QB * 3;           // 84
    float*    sw      = kp + 84;               // CAP
    unsigned* s1      = (unsigned*)(sw + CAP); // CAP  (q<<21 | k<<16 | ind)
    int*      kcnt    = (int*)(s1 + CAP);      // NB
    int*      kstart  = kcnt + NB;             // NB+1
    int*      koff    = kstart + NB + 1;       // NB

    const int tid   = threadIdx.x;
    const int qbase = blockIdx.x * QB;

    // ---- init ----
    for (int i = tid; i < QB * CH; i += NTHREADS) out_acc[i] = 0.f;
    for (int i = tid; i < QB * 3; i += NTHREADS) {
        int gi = qbase * 3 + i;
        qp[i] = (gi < N * 3) ? q_pts[gi] : 0.f;
    }
    for (int i = tid; i < KK * 3; i += NTHREADS) kp[i] = kpts[i];
    if (tid < NB) kcnt[tid] = 0;
    __syncthreads();

    // w_k > 0 requires |nb - kp_k| < EXT (0.8660254); max|kp| = 1.0
    const float TH2     = 1.8675f * 1.8675f;
    const float INV_EXT = 1.15470053837925f;

    // ---- pass A: count hits per (owner,k) bucket ----
    for (int p = tid; p < QB * 32; p += NTHREADS) {
        int q  = p >> 5, h = p & 31;
        int gq = qbase + q;
        if (gq >= N) continue;
        int ind = inds[gq * 32 + h];
        if ((unsigned)ind >= (unsigned)M) continue;
        float dx = s_pts[ind * 3 + 0] - qp[q * 3 + 0];
        float dy = s_pts[ind * 3 + 1] - qp[q * 3 + 1];
        float dz = s_pts[ind * 3 + 2] - qp[q * 3 + 2];
        if (dx * dx + dy * dy + dz * dz >= TH2) continue;
        #pragma unroll
        for (int k = 0; k < KK; k++) {
            float ex = dx - kp[k * 3 + 0];
            float ey = dy - kp[k * 3 + 1];
            float ez = dz - kp[k * 3 + 2];
            float w  = 1.f - sqrtf(ex * ex + ey * ey + ez * ez) * INV_EXT;
            if (w > 0.f) atomicAdd(&kcnt[(q & 7) * KK + k], 1);
        }
    }
    __syncthreads();

    // ---- prefix sum over 216 buckets ----
    if (tid == 0) {
        int s = 0;
        for (int b = 0; b < NB; b++) { kstart[b] = s; koff[b] = s; s += kcnt[b]; }
        kstart[NB] = s;
    }
    __syncthreads();

    // ---- pass B: recompute + place into sorted position ----
    for (int p = tid; p < QB * 32; p += NTHREADS) {
        int q  = p >> 5, h = p & 31;
        int gq = qbase + q;
        if (gq >= N) continue;
        int ind = inds[gq * 32 + h];
        if ((unsigned)ind >= (unsigned)M) continue;
        float dx = s_pts[ind * 3 + 0] - qp[q * 3 + 0];
        float dy = s_pts[ind * 3 + 1] - qp[q * 3 + 1];
        float dz = s_pts[ind * 3 + 2] - qp[q * 3 + 2];
        if (dx * dx + dy * dy + dz * dz >= TH2) continue;
        #pragma unroll
        for (int k = 0; k < KK; k++) {
            float ex = dx - kp[k * 3 + 0];
            float ey = dy - kp[k * 3 + 1];
            float ez = dz - kp[k * 3 + 2];
            float w  = 1.f - sqrtf(ex * ex + ey * ey + ez * ez) * INV_EXT;
            if (w > 0.f) {
                int pos = atomicAdd(&koff[(q & 7) * KK + k], 1);
                if (pos < CAP) {
                    s1[pos] = ((unsigned)q << 21) | ((unsigned)k << 16) | (unsigned)ind;
                    sw[pos] = w;
                } else {
                    // correctness fallback (statistically unreachable)
                    const float* xr = x + (size_t)ind * CH;
                    const float* wk = W + (size_t)k * CH * CH;
                    for (int o = 0; o < CH; o++) {
                        float a = 0.f;
                        for (int c = 0; c < CH; c++) a += xr[c] * wk[c * CH + o];
                        atomicAdd(&out_acc[q * CH + o], w * a);
                    }
                }
            }
        }
    }
    __syncthreads();

    // ---- phase 3: each warp walks its own k-sorted segment, no syncs ----
    // Warp wid owns queries with q&7 == wid  -> race-free out_acc RMW.
    const int wid = tid >> 5, lane = tid & 31;
    int e  = min(kstart[wid * KK], CAP);
    int we = min(kstart[wid * KK + KK], CAP);

    while (e < we) {
        unsigned p0 = s1[e];
        int k = (p0 >> 16) & 31;
        bool pair = (e + 1 < we) && (((s1[e + 1] >> 16) & 31) == (unsigned)k);
        const float* wk = W + (size_t)k * CH * CH;

        if (pair) {
            unsigned p1 = s1[e + 1];
            int q0 = p0 >> 21,      q1 = p1 >> 21;
            int i0 = p0 & 0xFFFF,   i1 = p1 & 0xFFFF;
            float wt0 = sw[e], wt1 = sw[e + 1];
            const float4* x0 = (const float4*)(x + (size_t)i0 * CH);
            const float4* x1 = (const float4*)(x + (size_t)i1 * CH);
            float aA0 = 0.f, aA1 = 0.f, aB0 = 0.f, aB1 = 0.f;
            float bA0 = 0.f, bA1 = 0.f, bB0 = 0.f, bB1 = 0.f;
            #pragma unroll
            for (int c4 = 0; c4 < 16; c4++) {
                float4 xa = __ldg(x0 + c4);
                float4 xb = __ldg(x1 + c4);
                const float2* r = (const float2*)(wk + c4 * 4 * CH);
                float2 w0 = __ldg(r + lane);
                float2 w1 = __ldg(r + 32 + lane);
                float2 w2 = __ldg(r + 64 + lane);
                float2 w3 = __ldg(r + 96 + lane);
                aA0 += xa.x * w0.x; aA1 += xa.x * w0.y;
                bA0 += xb.x * w0.x; bA1 += xb.x * w0.y;
                aB0 += xa.y * w1.x; aB1 += xa.y * w1.y;
                bB0 += xb.y * w1.x; bB1 += xb.y * w1.y;
                aA0 += xa.z * w2.x; aA1 += xa.z * w2.y;
                bA0 += xb.z * w2.x; bA1 += xb.z * w2.y;
                aB0 += xa.w * w3.x; aB1 += xa.w * w3.y;
                bB0 += xb.w * w3.x; bB1 += xb.w * w3.y;
            }
            out_acc[q0 * CH + 2 * lane]     += wt0 * (aA0 + aB0);
            out_acc[q0 * CH + 2 * lane + 1] += wt0 * (aA1 + aB1);
            out_acc[q1 * CH + 2 * lane]     += wt1 * (bA0 + bB0);
            out_acc[q1 * CH + 2 * lane + 1] += wt1 * (bA1 + bB1);
            e += 2;
        } else {
            int   q0  = p0 >> 21;
            int   i0  = p0 & 0xFFFF;
            float wt0 = sw[e];
            const float4* x0 = (const float4*)(x + (size_t)i0 * CH);
            float aA0 = 0.f, aA1 = 0.f, aB0 = 0.f, aB1 = 0.f;
            #pragma unroll
            for (int c4 = 0; c4 < 16; c4++) {
                float4 xa = __ldg(x0 + c4);
                const float2* r = (const float2*)(wk + c4 * 4 * CH);
                float2 w0 = __ldg(r + lane);
                float2 w1 = __ldg(r + 32 + lane);
                float2 w2 = __ldg(r + 64 + lane);
                float2 w3 = __ldg(r + 96 + lane);
                aA0 += xa.x * w0.x; aA1 += xa.x * w0.y;
                aB0 += xa.y * w1.x; aB1 += xa.y * w1.y;
                aA0 += xa.z * w2.x; aA1 += xa.z * w2.y;
                aB0 += xa.w * w3.x; aB1 += xa.w * w3.y;
            }
            out_acc[q0 * CH + 2 * lane]     += wt0 * (aA0 + aB0);
            out_acc[q0 * CH + 2 * lane + 1] += wt0 * (aA1 + aB1);
            e += 1;
        }
    }
    __syncthreads();

    // ---- write out ----
    for (int i = tid; i < QB * CH; i += NTHREADS) {
        int q = i >> 6;
        if (qbase + q < N) out[(size_t)(qbase + q) * CH + (i & 63)] = out_acc[i];
    }
}

static int smem_bytes() {
    int f = QB * CH + QB * 3 + 84 + CAP;       // floats
    int u = CAP;                               // unsigned
    int i = NB + (NB + 1) + NB;                // ints
    return (f + u + i) * 4;
}

extern "C" void kernel_launch(void* const* d_in, const int* in_sizes, int n_in,
                              void* d_out, int out_size) {
    const float* q_pts = (const float*)d_in[0];
    const float* s_pts = (const float*)d_in[1];
    const int*   inds  = (const int*)d_in[2];
    const float* x     = (const float*)d_in[3];
    const float* W     = (const float*)d_in[4];
    const float* kpts  = (const float*)d_in[5];
    float*       out   = (float*)d_out;

    int N = in_sizes[0] / 3;
    int M = in_sizes[1] / 3;

    int smem = smem_bytes();
    cudaFuncSetAttribute(kpconv_kernel,
                         cudaFuncAttributeMaxDynamicSharedMemorySize, smem);
    int grid = (N + QB - 1) / QB;
    kpconv_kernel<<<grid, NTHREADS, smem>>>(q_pts, s_pts, inds, x, W, kpts,
                                            out, N, M);
}

// round 4
// speedup vs baseline: 3.4640x; 3.4640x over previous
#include <cuda_runtime.h>

#define KK    27
#define CH    64
#define CAPK  65536          // per-k entry capacity (expected ~8K)
#define EXT2  0.75f          // KP_EXTENT^2
#define INV_EXT 1.15470053837925f
#define TH2   (1.8675f * 1.8675f)

// global scratch (static __device__ — no runtime allocation)
__device__ unsigned g_pack[KK * CAPK];   // q<<16 | ind
__device__ float    g_w[KK * CAPK];
__device__ int      g_cnt[KK];

// ---------------- packed f32x2 helpers (Blackwell dual-FMA path) -----------
#define PACK2(d, lo, hi) \
    asm("mov.b64 %0, {%1, %2};" : "=l"(d) : "r"(__float_as_uint(lo)), "r"(__float_as_uint(hi)))
#define FMA2(acc, a, b) \
    asm("fma.rn.f32x2 %0, %1, %2, %0;" : "+l"(acc) : "l"(a), "l"(b))
#define UNPACK2(lo, hi, v) \
    asm("mov.b64 {%0, %1}, %2;" : "=r"(lo), "=r"(hi) : "l"(v))

__device__ __forceinline__ void red_add(float* p, float v) {
    asm volatile("red.global.add.f32 [%0], %1;" :: "l"(p), "f"(v) : "memory");
}

// ---------------- kernel 0: zero out + counters ----------------------------
__global__ void zero_kernel(float* __restrict__ out, int n4) {
    int i = blockIdx.x * blockDim.x + threadIdx.x;
    if (i < n4) ((float4*)out)[i] = make_float4(0.f, 0.f, 0.f, 0.f);
    if (blockIdx.x == 0 && threadIdx.x < KK) g_cnt[threadIdx.x] = 0;
}

// ---------------- kernel 1: build per-k entry lists ------------------------
__global__ __launch_bounds__(256) void build_kernel(
    const float* __restrict__ q_pts,   // [N,3]
    const float* __restrict__ s_pts,   // [M,3]
    const int*   __restrict__ inds,    // [N,32]
    const float* __restrict__ x,       // [M,64]  (fallback only)
    const float* __restrict__ W,       // [27,64,64] (fallback only)
    const float* __restrict__ kpts,    // [27,3]
    float* __restrict__ out,           // fallback only
    int N, int M)
{
    int p = blockIdx.x * blockDim.x + threadIdx.x;
    if (p >= N * 32) return;
    int q = p >> 5;
    int ind = inds[p];
    if ((unsigned)ind >= (unsigned)M) return;        // shadow neighbor

    float qx = q_pts[q * 3 + 0], qy = q_pts[q * 3 + 1], qz = q_pts[q * 3 + 2];
    float dx = s_pts[ind * 3 + 0] - qx;
    float dy = s_pts[ind * 3 + 1] - qy;
    float dz = s_pts[ind * 3 + 2] - qz;
    if (dx * dx + dy * dy + dz * dz >= TH2) return;  // ~97% reject

    #pragma unroll 1
    for (int k = 0; k < KK; k++) {
        float ex = dx - kpts[k * 3 + 0];
        float ey = dy - kpts[k * 3 + 1];
        float ez = dz - kpts[k * 3 + 2];
        float dd = ex * ex + ey * ey + ez * ez;
        if (dd < EXT2) {
            float w = 1.f - sqrtf(dd) * INV_EXT;
            int pos = atomicAdd(&g_cnt[k], 1);
            if (pos < CAPK) {
                g_pack[k * CAPK + pos] = ((unsigned)q << 16) | (unsigned)ind;
                g_w[k * CAPK + pos]    = w;
            } else {
                // correctness fallback (statistically unreachable)
                const float* xr = x + (size_t)ind * CH;
                const float* wk = W + (size_t)k * CH * CH;
                for (int o = 0; o < CH; o++) {
                    float a = 0.f;
                    for (int c = 0; c < CH; c++) a += xr[c] * wk[c * CH + o];
                    atomicAdd(&out[(size_t)q * CH + o], w * a);
                }
            }
        }
    }
}

// ---------------- kernel 2: per-k batched GEMM + scatter -------------------
// grid (27, SLICES), 256 threads. Tile = 128 rows x 64 out, k-dim 64.
// Thread (g = tid>>3 in 0..31, cg = tid&7): rows 4g..4g+3, cols 8cg..8cg+7.
#define SLICES 11

__global__ __launch_bounds__(256, 2) void gemm_kernel(
    const float* __restrict__ W,       // [27,64,64]
    const float* __restrict__ x,       // [M,64]
    float* __restrict__ out)           // [N,64]
{
    extern __shared__ float smem[];
    float* Ws = smem;             // 64*64
    float* xs = Ws + CH * CH;     // [64][128] transposed, w-scaled
    int*   qs = (int*)(xs + CH * 128);  // 128

    const int k   = blockIdx.x;
    const int tid = threadIdx.x;
    const int g   = tid >> 3;     // row group 0..31
    const int cg  = tid & 7;      // col group 0..7
    const int r   = tid & 127;    // gather row
    const int c40 = tid >> 7;     // 0 or 1

    const int R = min(g_cnt[k], CAPK);
    if (R == 0) return;
    const int ntiles = (R + 127) >> 7;

    // stage W[k] once
    {
        const float4* src = (const float4*)(W + (size_t)k * CH * CH);
        float4*       dst = (float4*)Ws;
        for (int i = tid; i < (CH * CH) / 4; i += 256) dst[i] = src[i];
    }

    for (int t = blockIdx.y; t < ntiles; t += SLICES) {
        int base = t << 7;
        bool val = (base + r) < R;
        unsigned pk = val ? g_pack[k * CAPK + base + r] : 0u;
        float    wt = val ? g_w[k * CAPK + base + r]    : 0.f;
        int      ind = pk & 0xFFFFu;
        if (tid < 128) qs[r] = (int)(pk >> 16);
        __syncthreads();   // also guards xs reuse from previous tile

        // gather: xs[c][r] = wt * x[ind][c]   (transposed, pre-scaled)
        {
            const float4* xr = (const float4*)(x + (size_t)ind * CH);
            #pragma unroll
            for (int t2 = 0; t2 < 8; t2++) {
                int c4 = c40 + 2 * t2;
                float4 v = __ldg(xr + c4);
                xs[(4 * c4 + 0) * 128 + r] = wt * v.x;
                xs[(4 * c4 + 1) * 128 + r] = wt * v.y;
                xs[(4 * c4 + 2) * 128 + r] = wt * v.z;
                xs[(4 * c4 + 3) * 128 + r] = wt * v.w;
            }
        }
        __syncthreads();

        // 128x64x64 register-tiled GEMM with dual-FMA (f32x2)
        unsigned long long acc[4][4];
        #pragma unroll
        for (int a = 0; a < 4; a++)
            #pragma unroll
            for (int b = 0; b < 4; b++) acc[a][b] = 0ull;

        #pragma unroll 4
        for (int cin = 0; cin < CH; cin++) {
            float4 xv = *(const float4*)&xs[cin * 128 + 4 * g];
            float4 wa = *(const float4*)&Ws[cin * CH + 8 * cg];
            float4 wb = *(const float4*)&Ws[cin * CH + 8 * cg + 4];
            unsigned long long pw0, pw1, pw2, pw3, px;
            PACK2(pw0, wa.x, wa.y);
            PACK2(pw1, wa.z, wa.w);
            PACK2(pw2, wb.x, wb.y);
            PACK2(pw3, wb.z, wb.w);
            PACK2(px, xv.x, xv.x);
            FMA2(acc[0][0], px, pw0); FMA2(acc[0][1], px, pw1);
            FMA2(acc[0][2], px, pw2); FMA2(acc[0][3], px, pw3);
            PACK2(px, xv.y, xv.y);
            FMA2(acc[1][0], px, pw0); FMA2(acc[1][1], px, pw1);
            FMA2(acc[1][2], px, pw2); FMA2(acc[1][3], px, pw3);
            PACK2(px, xv.z, xv.z);
            FMA2(acc[2][0], px, pw0); FMA2(acc[2][1], px, pw1);
            FMA2(acc[2][2], px, pw2); FMA2(acc[2][3], px, pw3);
            PACK2(px, xv.w, xv.w);
            FMA2(acc[3][0], px, pw0); FMA2(acc[3][1], px, pw1);
            FMA2(acc[3][2], px, pw2); FMA2(acc[3][3], px, pw3);
        }

        // scatter to out[q] via fire-and-forget global reductions
        #pragma unroll
        for (int rr = 0; rr < 4; rr++) {
            int row = 4 * g + rr;
            if (base + row < R) {
                float* op = out + (size_t)qs[row] * CH + 8 * cg;
                #pragma unroll
                for (int cp = 0; cp < 4; cp++) {
                    unsigned lo, hi;
                    UNPACK2(lo, hi, acc[rr][cp]);
                    red_add(op + 2 * cp,     __uint_as_float(lo));
                    red_add(op + 2 * cp + 1, __uint_as_float(hi));
                }
            }
        }
        __syncthreads();   // protect qs/xs before next tile's writes
    }
}

// ---------------- launcher --------------------------------------------------
extern "C" void kernel_launch(void* const* d_in, const int* in_sizes, int n_in,
                              void* d_out, int out_size) {
    const float* q_pts = (const float*)d_in[0];
    const float* s_pts = (const float*)d_in[1];
    const int*   inds  = (const int*)d_in[2];
    const float* x     = (const float*)d_in[3];
    const float* W     = (const float*)d_in[4];
    const float* kpts  = (const float*)d_in[5];
    float*       out   = (float*)d_out;

    int N = in_sizes[0] / 3;
    int M = in_sizes[1] / 3;

    // 0) zero output + counters
    int n4 = out_size / 4;
    zero_kernel<<<(n4 + 255) / 256, 256>>>(out, n4);

    // 1) build per-k entry lists
    int pairs = N * 32;
    build_kernel<<<(pairs + 255) / 256, 256>>>(q_pts, s_pts, inds, x, W, kpts,
                                               out, N, M);

    // 2) per-k GEMM + scatter
    int smem = (CH * CH + CH * 128) * 4 + 128 * 4;   // 49664 B
    cudaFuncSetAttribute(gemm_kernel,
                         cudaFuncAttributeMaxDynamicSharedMemorySize, smem);
    dim3 grid(KK, SLICES);
    gemm_kernel<<<grid, 256, smem>>>(W, x, out);
}

// round 5
// speedup vs baseline: 3.9125x; 1.1295x over previous
#include <cuda_runtime.h>

#define KK    27
#define CH    64
#define CAPK  65536          // per-k entry capacity (expected ~8K)
#define EXT2  0.75f          // KP_EXTENT^2
#define INV_EXT 1.15470053837925f
#define TH2   (1.8675f * 1.8675f)

// global scratch (static __device__ — no runtime allocation)
__device__ unsigned g_pack[KK * CAPK];   // q<<16 | ind
__device__ float    g_w[KK * CAPK];
__device__ int      g_cnt[KK];

// ---------------- packed f32x2 helpers (Blackwell dual-FMA path) -----------
#define PACK2(d, lo, hi) \
    asm("mov.b64 %0, {%1, %2};" : "=l"(d) : "r"(__float_as_uint(lo)), "r"(__float_as_uint(hi)))
#define FMA2(acc, a, b) \
    asm("fma.rn.f32x2 %0, %1, %2, %0;" : "+l"(acc) : "l"(a), "l"(b))
#define UNPACK2(lo, hi, v) \
    asm("mov.b64 {%0, %1}, %2;" : "=r"(lo), "=r"(hi) : "l"(v))

// vectorized fire-and-forget reduction (sm_90+): 4 floats per instruction
__device__ __forceinline__ void red_add_v4(float* p, float a, float b,
                                           float c, float d) {
    asm volatile("red.global.add.v4.f32 [%0], {%1, %2, %3, %4};"
                 :: "l"(p), "f"(a), "f"(b), "f"(c), "f"(d) : "memory");
}

__device__ __forceinline__ void red_add(float* p, float v) {
    asm volatile("red.global.add.f32 [%0], %1;" :: "l"(p), "f"(v) : "memory");
}

// ---------------- kernel 0: zero out + counters ----------------------------
__global__ void zero_kernel(float* __restrict__ out, int n4) {
    int i = blockIdx.x * blockDim.x + threadIdx.x;
    if (i < n4) ((float4*)out)[i] = make_float4(0.f, 0.f, 0.f, 0.f);
    if (blockIdx.x == 0 && threadIdx.x < KK) g_cnt[threadIdx.x] = 0;
}

// ---------------- kernel 1: build per-k entry lists ------------------------
__global__ __launch_bounds__(256) void build_kernel(
    const float* __restrict__ q_pts,   // [N,3]
    const float* __restrict__ s_pts,   // [M,3]
    const int*   __restrict__ inds,    // [N,32]
    const float* __restrict__ x,       // [M,64]  (fallback only)
    const float* __restrict__ W,       // [27,64,64] (fallback only)
    const float* __restrict__ kpts,    // [27,3]
    float* __restrict__ out,           // fallback only
    int N, int M)
{
    int p = blockIdx.x * blockDim.x + threadIdx.x;
    if (p >= N * 32) return;
    int q = p >> 5;
    int ind = inds[p];
    if ((unsigned)ind >= (unsigned)M) return;        // shadow neighbor

    float qx = q_pts[q * 3 + 0], qy = q_pts[q * 3 + 1], qz = q_pts[q * 3 + 2];
    float dx = s_pts[ind * 3 + 0] - qx;
    float dy = s_pts[ind * 3 + 1] - qy;
    float dz = s_pts[ind * 3 + 2] - qz;
    if (dx * dx + dy * dy + dz * dz >= TH2) return;  // ~97% reject

    #pragma unroll 1
    for (int k = 0; k < KK; k++) {
        float ex = dx - kpts[k * 3 + 0];
        float ey = dy - kpts[k * 3 + 1];
        float ez = dz - kpts[k * 3 + 2];
        float dd = ex * ex + ey * ey + ez * ez;
        if (dd < EXT2) {
            float w = 1.f - sqrtf(dd) * INV_EXT;
            int pos = atomicAdd(&g_cnt[k], 1);
            if (pos < CAPK) {
                g_pack[k * CAPK + pos] = ((unsigned)q << 16) | (unsigned)ind;
                g_w[k * CAPK + pos]    = w;
            } else {
                // correctness fallback (statistically unreachable)
                const float* xr = x + (size_t)ind * CH;
                const float* wk = W + (size_t)k * CH * CH;
                for (int o = 0; o < CH; o++) {
                    float a = 0.f;
                    for (int c = 0; c < CH; c++) a += xr[c] * wk[c * CH + o];
                    atomicAdd(&out[(size_t)q * CH + o], w * a);
                }
            }
        }
    }
}

// ---------------- kernel 2: per-k batched GEMM + scatter -------------------
// grid (27, SLICES), 256 threads. Tile = 128 rows x 64 out, k-dim 64.
// Thread (g = tid>>3 in 0..31, cg = tid&7): rows 4g..4g+3, cols 8cg..8cg+7.
#define SLICES 11

__global__ __launch_bounds__(256, 2) void gemm_kernel(
    const float* __restrict__ W,       // [27,64,64]
    const float* __restrict__ x,       // [M,64]
    float* __restrict__ out)           // [N,64]
{
    extern __shared__ float smem[];
    float* Ws = smem;             // 64*64
    float* xs = Ws + CH * CH;     // [64][128] transposed, w-scaled
    int*   qs = (int*)(xs + CH * 128);  // 128

    const int k   = blockIdx.x;
    const int tid = threadIdx.x;
    const int g   = tid >> 3;     // row group 0..31
    const int cg  = tid & 7;      // col group 0..7
    const int r   = tid & 127;    // gather row
    const int c40 = tid >> 7;     // 0 or 1

    const int R = min(g_cnt[k], CAPK);
    if (R == 0) return;
    const int ntiles = (R + 127) >> 7;

    // stage W[k] once
    {
        const float4* src = (const float4*)(W + (size_t)k * CH * CH);
        float4*       dst = (float4*)Ws;
        for (int i = tid; i < (CH * CH) / 4; i += 256) dst[i] = src[i];
    }

    for (int t = blockIdx.y; t < ntiles; t += SLICES) {
        int base = t << 7;
        bool val = (base + r) < R;
        unsigned pk = val ? g_pack[k * CAPK + base + r] : 0u;
        float    wt = val ? g_w[k * CAPK + base + r]    : 0.f;
        int      ind = pk & 0xFFFFu;
        if (tid < 128) qs[r] = (int)(pk >> 16);
        __syncthreads();   // also guards xs reuse from previous tile

        // gather: xs[c][r] = wt * x[ind][c]   (transposed, pre-scaled)
        {
            const float4* xr = (const float4*)(x + (size_t)ind * CH);
            #pragma unroll
            for (int t2 = 0; t2 < 8; t2++) {
                int c4 = c40 + 2 * t2;
                float4 v = __ldg(xr + c4);
                xs[(4 * c4 + 0) * 128 + r] = wt * v.x;
                xs[(4 * c4 + 1) * 128 + r] = wt * v.y;
                xs[(4 * c4 + 2) * 128 + r] = wt * v.z;
                xs[(4 * c4 + 3) * 128 + r] = wt * v.w;
            }
        }
        __syncthreads();

        // 128x64x64 register-tiled GEMM with dual-FMA (f32x2)
        unsigned long long acc[4][4];
        #pragma unroll
        for (int a = 0; a < 4; a++)
            #pragma unroll
            for (int b = 0; b < 4; b++) acc[a][b] = 0ull;

        #pragma unroll 4
        for (int cin = 0; cin < CH; cin++) {
            float4 xv = *(const float4*)&xs[cin * 128 + 4 * g];
            float4 wa = *(const float4*)&Ws[cin * CH + 8 * cg];
            float4 wb = *(const float4*)&Ws[cin * CH + 8 * cg + 4];
            unsigned long long pw0, pw1, pw2, pw3, px;
            PACK2(pw0, wa.x, wa.y);
            PACK2(pw1, wa.z, wa.w);
            PACK2(pw2, wb.x, wb.y);
            PACK2(pw3, wb.z, wb.w);
            PACK2(px, xv.x, xv.x);
            FMA2(acc[0][0], px, pw0); FMA2(acc[0][1], px, pw1);
            FMA2(acc[0][2], px, pw2); FMA2(acc[0][3], px, pw3);
            PACK2(px, xv.y, xv.y);
            FMA2(acc[1][0], px, pw0); FMA2(acc[1][1], px, pw1);
            FMA2(acc[1][2], px, pw2); FMA2(acc[1][3], px, pw3);
            PACK2(px, xv.z, xv.z);
            FMA2(acc[2][0], px, pw0); FMA2(acc[2][1], px, pw1);
            FMA2(acc[2][2], px, pw2); FMA2(acc[2][3], px, pw3);
            PACK2(px, xv.w, xv.w);
            FMA2(acc[3][0], px, pw0); FMA2(acc[3][1], px, pw1);
            FMA2(acc[3][2], px, pw2); FMA2(acc[3][3], px, pw3);
        }

        // scatter to out[q]: two v4 vector reductions per row per thread
        #pragma unroll
        for (int rr = 0; rr < 4; rr++) {
            int row = 4 * g + rr;
            if (base + row < R) {
                float* op = out + (size_t)qs[row] * CH + 8 * cg;
                unsigned a0, a1, a2, a3, b0, b1, b2, b3;
                UNPACK2(a0, a1, acc[rr][0]);
                UNPACK2(a2, a3, acc[rr][1]);
                UNPACK2(b0, b1, acc[rr][2]);
                UNPACK2(b2, b3, acc[rr][3]);
                red_add_v4(op,
                           __uint_as_float(a0), __uint_as_float(a1),
                           __uint_as_float(a2), __uint_as_float(a3));
                red_add_v4(op + 4,
                           __uint_as_float(b0), __uint_as_float(b1),
                           __uint_as_float(b2), __uint_as_float(b3));
            }
        }
        __syncthreads();   // protect qs/xs before next tile's writes
    }
}

// ---------------- launcher --------------------------------------------------
extern "C" void kernel_launch(void* const* d_in, const int* in_sizes, int n_in,
                              void* d_out, int out_size) {
    const float* q_pts = (const float*)d_in[0];
    const float* s_pts = (const float*)d_in[1];
    const int*   inds  = (const int*)d_in[2];
    const float* x     = (const float*)d_in[3];
    const float* W     = (const float*)d_in[4];
    const float* kpts  = (const float*)d_in[5];
    float*       out   = (float*)d_out;

    int N = in_sizes[0] / 3;
    int M = in_sizes[1] / 3;

    // 0) zero output + counters
    int n4 = out_size / 4;
    zero_kernel<<<(n4 + 255) / 256, 256>>>(out, n4);

    // 1) build per-k entry lists
    int pairs = N * 32;
    build_kernel<<<(pairs + 255) / 256, 256>>>(q_pts, s_pts, inds, x, W, kpts,
                                               out, N, M);

    // 2) per-k GEMM + scatter
    int smem = (CH * CH + CH * 128) * 4 + 128 * 4;   // 49664 B
    cudaFuncSetAttribute(gemm_kernel,
                         cudaFuncAttributeMaxDynamicSharedMemorySize, smem);
    dim3 grid(KK, SLICES);
    gemm_kernel<<<grid, 256, smem>>>(W, x, out);
}